// round 1
// baseline (speedup 1.0000x reference)
#include <cuda_runtime.h>

// PARCOR (reflection) coefficients -> LPC coefficients, Levinson step-up.
// Input:  k  [rows, 25] float32   (rows = 2,097,152)
// Output: a  [rows, 25] float32
//
// a = k; for m in 2..24: a[1:m] += k[m] * reverse(a[1:m])
// Note a[m] == k[m] at the time step m executes (position m first modified at
// step m+1), so the recurrence is self-contained in the row registers.

#define ORDER 25           // M+1 coefficients per row
#define RPB   256          // rows per block (one thread per row)
#define FLOATS_PER_BLOCK (RPB * ORDER)      // 6400 floats = 25600 bytes
#define VEC4_PER_BLOCK   (FLOATS_PER_BLOCK / 4)  // 1600 (25600 % 16 == 0)

__global__ __launch_bounds__(RPB)
void parcor_to_lpc_kernel(const float4* __restrict__ in4,
                          float4* __restrict__ out4,
                          int total_vec4)
{
    __shared__ float smem[FLOATS_PER_BLOCK];
    float4* smem4 = reinterpret_cast<float4*>(smem);

    const int t = threadIdx.x;
    const long long block_off4 = (long long)blockIdx.x * VEC4_PER_BLOCK;

    // ---- coalesced vectorized load: 25600 B contiguous per block ----
    #pragma unroll
    for (int i = 0; i < VEC4_PER_BLOCK / RPB + 1; ++i) {
        int idx = t + i * RPB;
        if (idx < VEC4_PER_BLOCK) {
            long long g = block_off4 + idx;
            if (g < total_vec4) smem4[idx] = in4[g];
        }
    }
    __syncthreads();

    // ---- per-thread row into registers (stride-25 smem reads: conflict-free) ----
    float a[ORDER];
    #pragma unroll
    for (int i = 0; i < ORDER; ++i) a[i] = smem[t * ORDER + i];

    // ---- Levinson step-up, fully unrolled (constant indices -> pure registers) ----
    #pragma unroll
    for (int m = 2; m < ORDER; ++m) {
        const float km = a[m];          // == k[m] at this step
        #pragma unroll
        for (int j = 1; 2 * j < m; ++j) {
            const float tj = a[j];
            const float tk = a[m - j];
            a[j]     = fmaf(km, tk, tj);
            a[m - j] = fmaf(km, tj, tk);
        }
        if ((m & 1) == 0) {             // middle element when segment length odd
            const int j = m >> 1;
            a[j] = fmaf(km, a[j], a[j]);
        }
    }

    // ---- results back to smem, then coalesced vectorized store ----
    __syncthreads();   // all reads of the input staging done before overwrite
    #pragma unroll
    for (int i = 0; i < ORDER; ++i) smem[t * ORDER + i] = a[i];
    __syncthreads();

    #pragma unroll
    for (int i = 0; i < VEC4_PER_BLOCK / RPB + 1; ++i) {
        int idx = t + i * RPB;
        if (idx < VEC4_PER_BLOCK) {
            long long g = block_off4 + idx;
            if (g < total_vec4) out4[g] = smem4[idx];
        }
    }
}

extern "C" void kernel_launch(void* const* d_in, const int* in_sizes, int n_in,
                              void* d_out, int out_size)
{
    const float* k = (const float*)d_in[0];
    float* out = (float*)d_out;

    const int total_elems = in_sizes[0];          // rows * 25
    const int rows = total_elems / ORDER;
    const int total_vec4 = total_elems / 4;       // 52,428,800 / 4 — divisible
    const int grid = (rows + RPB - 1) / RPB;      // 8192 for the bench shape

    parcor_to_lpc_kernel<<<grid, RPB>>>(
        reinterpret_cast<const float4*>(k),
        reinterpret_cast<float4*>(out),
        total_vec4);
}

// round 2
// speedup vs baseline: 1.0820x; 1.0820x over previous
#include <cuda_runtime.h>
#include <cstdint>

// PARCOR -> LPC (Levinson step-up), 2,097,152 rows x 25 f32.
// HBM-bound: bulk-async (UBLKCP) tile in, register recurrence, bulk-async tile out.

#define ORDER 25
#define RPB   256                      // rows per block, one thread per row
#define TILE_FLOATS (RPB * ORDER)      // 6400
#define TILE_BYTES  (TILE_FLOATS * 4)  // 25600, % 16 == 0

__global__ __launch_bounds__(RPB, 7)
void parcor_to_lpc_bulk(const float* __restrict__ in, float* __restrict__ out)
{
    __shared__ __align__(128) float buf[TILE_FLOATS];
    __shared__ __align__(8) unsigned long long mbar;

    const int t = threadIdx.x;

    uint32_t buf_addr, mbar_addr;
    asm volatile("{ .reg .u64 a; cvta.to.shared.u64 a, %1; cvt.u32.u64 %0, a; }"
                 : "=r"(buf_addr) : "l"(buf));
    asm volatile("{ .reg .u64 a; cvta.to.shared.u64 a, %1; cvt.u32.u64 %0, a; }"
                 : "=r"(mbar_addr) : "l"(&mbar));

    const float* gsrc = in  + (size_t)blockIdx.x * TILE_FLOATS;
    float*       gdst = out + (size_t)blockIdx.x * TILE_FLOATS;

    // ---- init mbarrier, then single-thread bulk G->S copy of the whole tile ----
    if (t == 0) {
        asm volatile("mbarrier.init.shared.b64 [%0], 1;" :: "r"(mbar_addr) : "memory");
    }
    __syncthreads();
    if (t == 0) {
        asm volatile("mbarrier.arrive.expect_tx.shared.b64 _, [%0], %1;"
                     :: "r"(mbar_addr), "r"((uint32_t)TILE_BYTES) : "memory");
        asm volatile("cp.async.bulk.shared::cta.global.mbarrier::complete_tx::bytes "
                     "[%0], [%1], %2, [%3];"
                     :: "r"(buf_addr), "l"(gsrc), "r"((uint32_t)TILE_BYTES), "r"(mbar_addr)
                     : "memory");
    }

    // ---- all threads wait for tile arrival (acquire orders the LDS reads) ----
    {
        uint32_t done;
        asm volatile(
            "{\n\t"
            ".reg .pred p;\n\t"
            "mbarrier.try_wait.parity.acquire.cta.shared::cta.b64 p, [%1], 0;\n\t"
            "selp.b32 %0, 1, 0, p;\n\t"
            "}"
            : "=r"(done) : "r"(mbar_addr) : "memory");
        if (!done) {
            asm volatile(
                "{\n\t"
                ".reg .pred P1;\n\t"
                "WAIT_LOOP_%=:\n\t"
                "mbarrier.try_wait.parity.acquire.cta.shared::cta.b64 P1, [%0], 0, 0x989680;\n\t"
                "@P1 bra.uni WAIT_DONE_%=;\n\t"
                "bra.uni WAIT_LOOP_%=;\n\t"
                "WAIT_DONE_%=:\n\t"
                "}"
                :: "r"(mbar_addr) : "memory");
        }
    }

    // ---- row into registers (stride-25 word reads: gcd(25,32)=1, conflict-free) ----
    float a[ORDER];
    #pragma unroll
    for (int i = 0; i < ORDER; ++i) a[i] = buf[t * ORDER + i];

    // ---- Levinson step-up, fully unrolled ----
    // a[m] == k[m] when step m runs (index m first touched at step m+1).
    #pragma unroll
    for (int m = 2; m < ORDER; ++m) {
        const float km = a[m];
        #pragma unroll
        for (int j = 1; 2 * j < m; ++j) {
            const float tj = a[j];
            const float tk = a[m - j];
            a[j]     = fmaf(km, tk, tj);
            a[m - j] = fmaf(km, tj, tk);
        }
        if ((m & 1) == 0) {
            const int j = m >> 1;
            a[j] = fmaf(km, a[j], a[j]);
        }
    }

    // ---- write back to OWN smem slots (no cross-thread hazard -> no barrier first) ----
    #pragma unroll
    for (int i = 0; i < ORDER; ++i) buf[t * ORDER + i] = a[i];
    __syncthreads();

    // ---- single-thread bulk S->G store of the whole tile ----
    if (t == 0) {
        asm volatile("fence.proxy.async;" ::: "memory");
        asm volatile("cp.async.bulk.global.shared::cta.bulk_group [%0], [%1], %2;"
                     :: "l"(gdst), "r"(buf_addr), "r"((uint32_t)TILE_BYTES) : "memory");
        asm volatile("cp.async.bulk.commit_group;" ::: "memory");
        asm volatile("cp.async.bulk.wait_group 0;" ::: "memory");
    }
}

// Fallback for shapes not divisible by the tile (not hit by the bench shape):
// plain per-row scalar kernel.
__global__ void parcor_to_lpc_scalar(const float* __restrict__ in,
                                     float* __restrict__ out, int rows)
{
    int r = blockIdx.x * blockDim.x + threadIdx.x;
    if (r >= rows) return;
    float a[ORDER];
    #pragma unroll
    for (int i = 0; i < ORDER; ++i) a[i] = in[(size_t)r * ORDER + i];
    #pragma unroll
    for (int m = 2; m < ORDER; ++m) {
        const float km = a[m];
        #pragma unroll
        for (int j = 1; 2 * j < m; ++j) {
            const float tj = a[j];
            const float tk = a[m - j];
            a[j]     = fmaf(km, tk, tj);
            a[m - j] = fmaf(km, tj, tk);
        }
        if ((m & 1) == 0) { const int j = m >> 1; a[j] = fmaf(km, a[j], a[j]); }
    }
    #pragma unroll
    for (int i = 0; i < ORDER; ++i) out[(size_t)r * ORDER + i] = a[i];
}

extern "C" void kernel_launch(void* const* d_in, const int* in_sizes, int n_in,
                              void* d_out, int out_size)
{
    const float* k = (const float*)d_in[0];
    float* out = (float*)d_out;

    const int total_elems = in_sizes[0];
    const int rows = total_elems / ORDER;

    if (rows % RPB == 0) {
        parcor_to_lpc_bulk<<<rows / RPB, RPB>>>(k, out);
    } else {
        parcor_to_lpc_scalar<<<(rows + RPB - 1) / RPB, RPB>>>(k, out, rows);
    }
}